// round 7
// baseline (speedup 1.0000x reference)
#include <cuda_runtime.h>
#include <cuda_bf16.h>

#define DD     16
#define NHEAD  8
#define LAYERS 8
#define FFD    16
#define KW     35
#define SEQIN  3500
#define NP     100
#define SS     101
#define HSTR   20      // s_h row stride (16B-aligned rows)
#define QSTR   50      // qkv row stride (even -> 8B pairs; %32=18 -> 2-way STS)
#define NT     128
#define QB     7       // query rows per attention task
#define NBLK   15      // ceil(SS/QB) -> 8*15 = 120 tasks

typedef unsigned long long u64;

__device__ __forceinline__ float ex2f_fast(float x) {
    float y;
    asm("ex2.approx.ftz.f32 %0, %1;" : "=f"(y) : "f"(x));
    return y;
}
__device__ __forceinline__ float rcpf_fast(float x) {
    float y;
    asm("rcp.approx.ftz.f32 %0, %1;" : "=f"(y) : "f"(x));
    return y;
}
__device__ __forceinline__ u64 pk2(float lo, float hi) {
    u64 r; asm("mov.b64 %0, {%1, %2};" : "=l"(r) : "f"(lo), "f"(hi)); return r;
}
__device__ __forceinline__ void upk2(u64 v, float& lo, float& hi) {
    asm("mov.b64 {%0, %1}, %2;" : "=f"(lo), "=f"(hi) : "l"(v));
}
__device__ __forceinline__ u64 fma2_(u64 a, u64 b, u64 c) {
    u64 r; asm("fma.rn.f32x2 %0, %1, %2, %3;" : "=l"(r) : "l"(a), "l"(b), "l"(c)); return r;
}
__device__ __forceinline__ u64 mul2_(u64 a, u64 b) {
    u64 r; asm("mul.rn.f32x2 %0, %1, %2;" : "=l"(r) : "l"(a), "l"(b)); return r;
}

// packed 16-dot: a2 = 8 packed activation pairs (regs), w2 = smem weight row as u64*
__device__ __forceinline__ float dot16p(const u64* a2, const u64* __restrict__ w2, float bias) {
    u64 acc = pk2(bias, 0.f);
    #pragma unroll
    for (int j = 0; j < 8; j++) acc = fma2_(a2[j], w2[j], acc);
    float lo, hi; upk2(acc, lo, hi);
    return lo + hi;
}

__global__ __launch_bounds__(NT, 6) void TorrinE0_fused_kernel(
    const float* __restrict__ x,      const float* __restrict__ conv_w, const float* __restrict__ conv_b,
    const float* __restrict__ cls_emb,const float* __restrict__ Wqkv,   const float* __restrict__ bqkv,
    const float* __restrict__ Wo,     const float* __restrict__ bo,
    const float* __restrict__ W1,     const float* __restrict__ b1,
    const float* __restrict__ W2,     const float* __restrict__ b2,
    const float* __restrict__ ln1_g,  const float* __restrict__ ln1_b,
    const float* __restrict__ ln2_g,  const float* __restrict__ ln2_b,
    const float* __restrict__ lnf_g,  const float* __restrict__ lnf_b,
    const float* __restrict__ end_w,  const float* __restrict__ end_b,
    const float* __restrict__ head_w, const float* __restrict__ head_b,
    float* __restrict__ out)
{
    __shared__ __align__(16) float s_h  [SS * HSTR];
    __shared__ __align__(16) float s_qkv[SS * QSTR];  // also holds x (3500 <= 5050) during conv
    __shared__ __align__(16) float s_Wqkv[768];       // holds conv_w (560) during conv
    __shared__ __align__(16) float s_bqkv[48];
    __shared__ __align__(16) float s_Wo[256], s_W1[256], s_W2[256];
    __shared__ float s_bo[16],  s_b1[16], s_b2[16];
    __shared__ float s_ln[64];

    const int tid = threadIdx.x;
    const int b   = blockIdx.x;

    // ---------- stage x row + conv weights ----------
    {
        const float4* x4 = reinterpret_cast<const float4*>(x + (size_t)b * SEQIN);
        float4* q4 = reinterpret_cast<float4*>(s_qkv);
        for (int i = tid; i < SEQIN / 4; i += NT) q4[i] = x4[i];
    }
    for (int i = tid; i < DD * KW; i += NT) s_Wqkv[i] = conv_w[i];
    if (tid < DD) s_bqkv[tid] = conv_b[tid];
    __syncthreads();

    // ---------- conv patch embedding ----------
    for (int idx = tid; idx < NP * DD; idx += NT) {
        int p = idx >> 4, f = idx & 15;
        float acc = s_bqkv[f];
        const float* xp = &s_qkv[p * KW];
        const float* wf = &s_Wqkv[f * KW];
        #pragma unroll
        for (int k = 0; k < KW; k++) acc = fmaf(xp[k], wf[k], acc);
        s_h[(p + 1) * HSTR + f] = acc;
    }
    if (tid < DD) s_h[tid] = cls_emb[tid];
    __syncthreads();

    const float QSC = 1.44269504088896f * 0.707106781186547f; // log2e / sqrt(2)

    // ---------- transformer layers ----------
    for (int l = 0; l < LAYERS; l++) {
        for (int i = tid; i < 768; i += NT) s_Wqkv[i] = Wqkv[l * 768 + i];
        for (int i = tid; i < 256; i += NT) {
            s_Wo[i] = Wo[l * 256 + i];
            s_W1[i] = W1[l * 256 + i];
            s_W2[i] = W2[l * 256 + i];
        }
        if (tid < 48) s_bqkv[tid] = bqkv[l * 48 + tid];
        if (tid < 16) {
            s_bo[tid]      = bo[l * 16 + tid];
            s_b1[tid]      = b1[l * 16 + tid];
            s_b2[tid]      = b2[l * 16 + tid];
            s_ln[tid]      = ln1_g[l * 16 + tid];
            s_ln[16 + tid] = ln1_b[l * 16 + tid];
            s_ln[32 + tid] = ln2_g[l * 16 + tid];
            s_ln[48 + tid] = ln2_b[l * 16 + tid];
        }
        __syncthreads();

        // ---- QKV projection: h row in packed regs, weights broadcast LDS.64 ----
        if (tid < SS) {
            const float4* h4 = reinterpret_cast<const float4*>(&s_h[tid * HSTR]);
            float4 hr[4] = {h4[0], h4[1], h4[2], h4[3]};
            const float* hs = reinterpret_cast<const float*>(hr);
            u64 h2[8];
            #pragma unroll
            for (int j = 0; j < 8; j++) h2[j] = pk2(hs[2*j], hs[2*j+1]);
            const u64* w2 = reinterpret_cast<const u64*>(s_Wqkv);

            float* qrow = &s_qkv[tid * QSTR];
            #pragma unroll
            for (int e = 0; e < 48; e++)
                qrow[e] = dot16p(h2, w2 + e * 8, s_bqkv[e]);
        }
        __syncthreads();

        // ---- attention: single-pass softmax, packed (x,y) per score ----
        {
            const bool active = (tid < NHEAD * NBLK);
            int hh = 0, s0 = 0;
            u64 q2[QB], c2[QB];
            float den[QB];
            if (active) {
                hh = tid / NBLK;
                s0 = (tid - hh * NBLK) * QB;
                #pragma unroll
                for (int i = 0; i < QB; i++) {
                    int s = s0 + i;
                    if (s < SS) {
                        float2 t = *reinterpret_cast<const float2*>(&s_qkv[s * QSTR + 2*hh]);
                        q2[i] = pk2(t.x * QSC, t.y * QSC);
                    } else q2[i] = 0ull;
                    c2[i] = 0ull;
                    den[i] = 0.f;
                }
            }
            // all q values consumed before ctx overwrites the q columns
            __syncthreads();
            if (active) {
                for (int t = 0; t < SS; t++) {
                    u64 k2 = *reinterpret_cast<const u64*>(&s_qkv[t * QSTR + 16 + 2*hh]);
                    u64 v2 = *reinterpret_cast<const u64*>(&s_qkv[t * QSTR + 32 + 2*hh]);
                    #pragma unroll
                    for (int i = 0; i < QB; i++) {
                        u64 m2 = mul2_(q2[i], k2);
                        float lo, hi; upk2(m2, lo, hi);
                        float e = ex2f_fast(lo + hi);
                        den[i] += e;
                        c2[i] = fma2_(pk2(e, e), v2, c2[i]);
                    }
                }
                #pragma unroll
                for (int i = 0; i < QB; i++) {
                    int s = s0 + i;
                    if (s < SS) {
                        float cx, cy; upk2(c2[i], cx, cy);
                        float inv = rcpf_fast(den[i]);
                        float2 o; o.x = cx * inv; o.y = cy * inv;
                        // ctx goes into the (dead) q columns 0..15
                        *reinterpret_cast<float2*>(&s_qkv[s * QSTR + 2*hh]) = o;
                    }
                }
            }
        }
        __syncthreads();

        // ---- Wo + residual + LN1 + FF1 + FF2 + residual + LN2, per row, packed ----
        if (tid < SS) {
            // ctx from qkv cols 0..15 as packed pairs (8B aligned: QSTR even)
            const u64* cptr = reinterpret_cast<const u64*>(&s_qkv[tid * QSTR]);
            u64 c2[8];
            #pragma unroll
            for (int j = 0; j < 8; j++) c2[j] = cptr[j];

            const float4* h4 = reinterpret_cast<const float4*>(&s_h[tid * HSTR]);
            float4 hr4[4] = {h4[0], h4[1], h4[2], h4[3]};
            const float* hs = reinterpret_cast<const float*>(hr4);

            const u64* wo2 = reinterpret_cast<const u64*>(s_Wo);
            float vv[16];
            float mu = 0.f;
            #pragma unroll
            for (int o = 0; o < 16; o++) {
                vv[o] = dot16p(c2, wo2 + o * 8, s_bo[o]) + hs[o];
                mu += vv[o];
            }
            mu *= 0.0625f;
            float var = 0.f;
            #pragma unroll
            for (int d = 0; d < 16; d++) { float t = vv[d] - mu; var = fmaf(t, t, var); }
            float r = rsqrtf(fmaf(var, 0.0625f, 1e-5f));

            float ln1s[16];
            #pragma unroll
            for (int d = 0; d < 16; d++)
                ln1s[d] = (vv[d] - mu) * r * s_ln[d] + s_ln[16 + d];
            u64 l2[8];
            #pragma unroll
            for (int j = 0; j < 8; j++) l2[j] = pk2(ln1s[2*j], ln1s[2*j+1]);

            const u64* w12 = reinterpret_cast<const u64*>(s_W1);
            float frs[16];
            #pragma unroll
            for (int f = 0; f < 16; f++)
                frs[f] = fmaxf(dot16p(l2, w12 + f * 8, s_b1[f]), 0.f);
            u64 f2[8];
            #pragma unroll
            for (int j = 0; j < 8; j++) f2[j] = pk2(frs[2*j], frs[2*j+1]);

            const u64* w22 = reinterpret_cast<const u64*>(s_W2);
            mu = 0.f;
            #pragma unroll
            for (int d = 0; d < 16; d++) {
                vv[d] = dot16p(f2, w22 + d * 8, s_b2[d]) + ln1s[d];
                mu += vv[d];
            }
            mu *= 0.0625f;
            var = 0.f;
            #pragma unroll
            for (int d = 0; d < 16; d++) { float t = vv[d] - mu; var = fmaf(t, t, var); }
            r = rsqrtf(fmaf(var, 0.0625f, 1e-5f));

            float4 ov[4];
            float* os = reinterpret_cast<float*>(ov);
            #pragma unroll
            for (int d = 0; d < 16; d++)
                os[d] = (vv[d] - mu) * r * s_ln[32 + d] + s_ln[48 + d];
            float4* oh = reinterpret_cast<float4*>(&s_h[tid * HSTR]);
            oh[0] = ov[0]; oh[1] = ov[1]; oh[2] = ov[2]; oh[3] = ov[3];
        }
        __syncthreads();
    }

    // ---------- final LN (cls row) ----------
    if (tid == 0) {
        float mu = 0.f;
        #pragma unroll
        for (int d = 0; d < 16; d++) mu += s_h[d];
        mu *= 0.0625f;
        float var = 0.f;
        #pragma unroll
        for (int d = 0; d < 16; d++) { float t = s_h[d] - mu; var = fmaf(t, t, var); }
        float r = rsqrtf(fmaf(var, 0.0625f, 1e-5f));
        #pragma unroll
        for (int d = 0; d < 16; d++)
            s_qkv[d] = (s_h[d] - mu) * r * lnf_g[d] + lnf_b[d];
    }
    __syncthreads();

    // ---------- end projection (fused with head weight) ----------
    if (tid < 100) {
        float acc = end_b[tid];
        #pragma unroll
        for (int d = 0; d < 16; d++) acc = fmaf(s_qkv[d], end_w[tid * 16 + d], acc);
        s_qkv[64 + tid] = acc * head_w[tid];
    }
    __syncthreads();

    // ---------- head sum + sigmoid ----------
    if (tid == 0) {
        float acc = head_b[0];
        #pragma unroll 4
        for (int j = 0; j < 100; j++) acc += s_qkv[64 + j];
        out[b] = 1.f / (1.f + ex2f_fast(-acc * 1.44269504088896f));
    }
}

extern "C" void kernel_launch(void* const* d_in, const int* in_sizes, int n_in,
                              void* d_out, int out_size) {
    const float* x       = (const float*)d_in[0];
    const float* conv_w  = (const float*)d_in[1];
    const float* conv_b  = (const float*)d_in[2];
    const float* cls_emb = (const float*)d_in[3];
    const float* Wqkv    = (const float*)d_in[4];
    const float* bqkv    = (const float*)d_in[5];
    const float* Wo      = (const float*)d_in[6];
    const float* bo      = (const float*)d_in[7];
    const float* W1      = (const float*)d_in[8];
    const float* b1      = (const float*)d_in[9];
    const float* W2      = (const float*)d_in[10];
    const float* b2      = (const float*)d_in[11];
    const float* ln1_g   = (const float*)d_in[12];
    const float* ln1_b   = (const float*)d_in[13];
    const float* ln2_g   = (const float*)d_in[14];
    const float* ln2_b   = (const float*)d_in[15];
    const float* lnf_g   = (const float*)d_in[16];
    const float* lnf_b   = (const float*)d_in[17];
    const float* end_w   = (const float*)d_in[18];
    const float* end_b   = (const float*)d_in[19];
    const float* head_w  = (const float*)d_in[20];
    const float* head_b  = (const float*)d_in[21];

    int B = in_sizes[0] / SEQIN;

    TorrinE0_fused_kernel<<<B, NT>>>(
        x, conv_w, conv_b, cls_emb, Wqkv, bqkv, Wo, bo, W1, b1, W2, b2,
        ln1_g, ln1_b, ln2_g, ln2_b, lnf_g, lnf_b, end_w, end_b, head_w, head_b,
        (float*)d_out);
}

// round 8
// speedup vs baseline: 1.1177x; 1.1177x over previous
#include <cuda_runtime.h>
#include <cuda_bf16.h>

#define DD     16
#define NHEAD  8
#define LAYERS 8
#define FFD    16
#define KW     35
#define SEQIN  3500
#define NP     100
#define SS     101
#define HSTR   20      // s_h row stride (16B-aligned rows)
#define NT     128
#define QB     7       // query rows per attention task
#define NBLK   15      // ceil(SS/QB) -> 8*15 = 120 tasks
#define TSTR   104     // per-head slot stride in s_att regions (even)

// s_att float regions (each 8 heads * TSTR floats = 832)
#define QX_OFF 0
#define QY_OFF 832
#define KX_OFF 1664
#define KY_OFF 2496
#define VX_OFF 3328
#define VY_OFF 4160
#define ATT_SZ 4992    // also holds x (3500) during conv

typedef unsigned long long u64;

__device__ __forceinline__ float ex2f_fast(float x) {
    float y;
    asm("ex2.approx.ftz.f32 %0, %1;" : "=f"(y) : "f"(x));
    return y;
}
__device__ __forceinline__ float rcpf_fast(float x) {
    float y;
    asm("rcp.approx.ftz.f32 %0, %1;" : "=f"(y) : "f"(x));
    return y;
}
__device__ __forceinline__ u64 pk2(float lo, float hi) {
    u64 r; asm("mov.b64 %0, {%1, %2};" : "=l"(r) : "f"(lo), "f"(hi)); return r;
}
__device__ __forceinline__ void upk2(u64 v, float& lo, float& hi) {
    asm("mov.b64 {%0, %1}, %2;" : "=f"(lo), "=f"(hi) : "l"(v));
}
__device__ __forceinline__ u64 fma2_(u64 a, u64 b, u64 c) {
    u64 r; asm("fma.rn.f32x2 %0, %1, %2, %3;" : "=l"(r) : "l"(a), "l"(b), "l"(c)); return r;
}
__device__ __forceinline__ u64 mul2_(u64 a, u64 b) {
    u64 r; asm("mul.rn.f32x2 %0, %1, %2;" : "=l"(r) : "l"(a), "l"(b)); return r;
}
__device__ __forceinline__ u64 add2_(u64 a, u64 b) {
    u64 r; asm("add.rn.f32x2 %0, %1, %2;" : "=l"(r) : "l"(a), "l"(b)); return r;
}

// packed 16-dot: a2 = 8 packed activation pairs (regs), w2 = smem weight row as u64*
__device__ __forceinline__ float dot16p(const u64* a2, const u64* __restrict__ w2, float bias) {
    u64 acc = pk2(bias, 0.f);
    #pragma unroll
    for (int j = 0; j < 8; j++) acc = fma2_(a2[j], w2[j], acc);
    float lo, hi; upk2(acc, lo, hi);
    return lo + hi;
}

__global__ __launch_bounds__(NT, 5) void TorrinE0_fused_kernel(
    const float* __restrict__ x,      const float* __restrict__ conv_w, const float* __restrict__ conv_b,
    const float* __restrict__ cls_emb,const float* __restrict__ Wqkv,   const float* __restrict__ bqkv,
    const float* __restrict__ Wo,     const float* __restrict__ bo,
    const float* __restrict__ W1,     const float* __restrict__ b1,
    const float* __restrict__ W2,     const float* __restrict__ b2,
    const float* __restrict__ ln1_g,  const float* __restrict__ ln1_b,
    const float* __restrict__ ln2_g,  const float* __restrict__ ln2_b,
    const float* __restrict__ lnf_g,  const float* __restrict__ lnf_b,
    const float* __restrict__ end_w,  const float* __restrict__ end_b,
    const float* __restrict__ head_w, const float* __restrict__ head_b,
    float* __restrict__ out)
{
    __shared__ __align__(16) float s_h  [SS * HSTR];
    __shared__ __align__(16) float s_att[ATT_SZ];
    __shared__ __align__(16) float s_Wqkv[768];       // holds conv_w (560) during conv
    __shared__ __align__(16) float s_bqkv[48];
    __shared__ __align__(16) float s_Wo[256], s_W1[256], s_W2[256];
    __shared__ float s_bo[16],  s_b1[16], s_b2[16];
    __shared__ float s_ln[64];

    const int tid = threadIdx.x;
    const int b   = blockIdx.x;

    // ---------- stage x row + conv weights ----------
    {
        const float4* x4 = reinterpret_cast<const float4*>(x + (size_t)b * SEQIN);
        float4* q4 = reinterpret_cast<float4*>(s_att);
        for (int i = tid; i < SEQIN / 4; i += NT) q4[i] = x4[i];
    }
    for (int i = tid; i < DD * KW; i += NT) s_Wqkv[i] = conv_w[i];
    if (tid < DD) s_bqkv[tid] = conv_b[tid];
    __syncthreads();

    // ---------- conv patch embedding ----------
    for (int idx = tid; idx < NP * DD; idx += NT) {
        int p = idx >> 4, f = idx & 15;
        float acc = s_bqkv[f];
        const float* xp = &s_att[p * KW];
        const float* wf = &s_Wqkv[f * KW];
        #pragma unroll
        for (int k = 0; k < KW; k++) acc = fmaf(xp[k], wf[k], acc);
        s_h[(p + 1) * HSTR + f] = acc;
    }
    if (tid < DD) s_h[tid] = cls_emb[tid];
    __syncthreads();

    // zero-pad slot SS (t=101) of K/V arrays once: k=0 -> score 0 -> e=1; v=0
    // (compensated by den -= 1 after the loop). These slots are never
    // overwritten by later phases.
    if (tid < NHEAD) {
        s_att[KX_OFF + tid * TSTR + SS] = 0.f;
        s_att[KY_OFF + tid * TSTR + SS] = 0.f;
        s_att[VX_OFF + tid * TSTR + SS] = 0.f;
        s_att[VY_OFF + tid * TSTR + SS] = 0.f;
    }

    const float QSC = 1.44269504088896f * 0.707106781186547f; // log2e / sqrt(2)

    // ---------- transformer layers ----------
    for (int l = 0; l < LAYERS; l++) {
        for (int i = tid; i < 768; i += NT) s_Wqkv[i] = Wqkv[l * 768 + i];
        for (int i = tid; i < 256; i += NT) {
            s_Wo[i] = Wo[l * 256 + i];
            s_W1[i] = W1[l * 256 + i];
            s_W2[i] = W2[l * 256 + i];
        }
        if (tid < 48) s_bqkv[tid] = bqkv[l * 48 + tid];
        if (tid < 16) {
            s_bo[tid]      = bo[l * 16 + tid];
            s_b1[tid]      = b1[l * 16 + tid];
            s_b2[tid]      = b2[l * 16 + tid];
            s_ln[tid]      = ln1_g[l * 16 + tid];
            s_ln[16 + tid] = ln1_b[l * 16 + tid];
            s_ln[32 + tid] = ln2_g[l * 16 + tid];
            s_ln[48 + tid] = ln2_b[l * 16 + tid];
        }
        __syncthreads();

        // ---- QKV projection: h row in packed regs; ALL outputs stored
        //      transposed (stride-1 across lanes -> conflict-free STS) ----
        if (tid < SS) {
            const float4* h4 = reinterpret_cast<const float4*>(&s_h[tid * HSTR]);
            float4 hr[4] = {h4[0], h4[1], h4[2], h4[3]};
            const float* hs = reinterpret_cast<const float*>(hr);
            u64 h2[8];
            #pragma unroll
            for (int j = 0; j < 8; j++) h2[j] = pk2(hs[2*j], hs[2*j+1]);
            const u64* w2 = reinterpret_cast<const u64*>(s_Wqkv);

            #pragma unroll
            for (int hh = 0; hh < NHEAD; hh++) {
                s_att[QX_OFF + hh * TSTR + tid] = dot16p(h2, w2 + (2*hh)          * 8, s_bqkv[2*hh]);
                s_att[QY_OFF + hh * TSTR + tid] = dot16p(h2, w2 + (2*hh + 1)      * 8, s_bqkv[2*hh + 1]);
                s_att[KX_OFF + hh * TSTR + tid] = dot16p(h2, w2 + (16 + 2*hh)     * 8, s_bqkv[16 + 2*hh]);
                s_att[KY_OFF + hh * TSTR + tid] = dot16p(h2, w2 + (16 + 2*hh + 1) * 8, s_bqkv[16 + 2*hh + 1]);
                s_att[VX_OFF + hh * TSTR + tid] = dot16p(h2, w2 + (32 + 2*hh)     * 8, s_bqkv[32 + 2*hh]);
                s_att[VY_OFF + hh * TSTR + tid] = dot16p(h2, w2 + (32 + 2*hh + 1) * 8, s_bqkv[32 + 2*hh + 1]);
            }
        }
        __syncthreads();

        // ---- attention: packed over t-pairs, single-pass softmax ----
        {
            const bool active = (tid < NHEAD * NBLK);
            int hh = 0, s0 = 0;
            u64 qx2[QB], qy2[QB];
            if (active) {
                hh = tid / NBLK;
                s0 = (tid - hh * NBLK) * QB;
                #pragma unroll
                for (int i = 0; i < QB; i++) {
                    int s = s0 + i;
                    float qx = s_att[QX_OFF + hh * TSTR + s] * QSC;
                    float qy = s_att[QY_OFF + hh * TSTR + s] * QSC;
                    qx2[i] = pk2(qx, qx);
                    qy2[i] = pk2(qy, qy);
                }
            }
            // all q loads complete before ctx overwrites the QX/QY region
            __syncthreads();
            if (active) {
                u64 den2[QB], cx2[QB], cy2[QB];
                #pragma unroll
                for (int i = 0; i < QB; i++) { den2[i] = 0ull; cx2[i] = 0ull; cy2[i] = 0ull; }

                const u64* kxp = reinterpret_cast<const u64*>(&s_att[KX_OFF + hh * TSTR]);
                const u64* kyp = reinterpret_cast<const u64*>(&s_att[KY_OFF + hh * TSTR]);
                const u64* vxp = reinterpret_cast<const u64*>(&s_att[VX_OFF + hh * TSTR]);
                const u64* vyp = reinterpret_cast<const u64*>(&s_att[VY_OFF + hh * TSTR]);

                for (int tp = 0; tp < (SS + 1) / 2; tp++) {   // 51 pairs, t=0..101 (101 padded)
                    u64 kx2 = kxp[tp], ky2 = kyp[tp];
                    u64 vx2 = vxp[tp], vy2 = vyp[tp];
                    #pragma unroll
                    for (int i = 0; i < QB; i++) {
                        u64 sc2 = fma2_(qy2[i], ky2, mul2_(qx2[i], kx2));
                        float sa, sb; upk2(sc2, sa, sb);
                        u64 e2 = pk2(ex2f_fast(sa), ex2f_fast(sb));
                        den2[i] = add2_(den2[i], e2);
                        cx2[i]  = fma2_(e2, vx2, cx2[i]);
                        cy2[i]  = fma2_(e2, vy2, cy2[i]);
                    }
                }
                u64* ctx_u64 = reinterpret_cast<u64*>(s_att);   // QX+QY region
                #pragma unroll
                for (int i = 0; i < QB; i++) {
                    int s = s0 + i;
                    if (s < SS) {
                        float d0, d1, a0, a1;
                        upk2(den2[i], d0, d1); float den = d0 + d1 - 1.f; // pad slot
                        upk2(cx2[i],  a0, a1); float cx  = a0 + a1;
                        upk2(cy2[i],  a0, a1); float cy  = a0 + a1;
                        float inv = rcpf_fast(den);
                        ctx_u64[hh * TSTR + s] = pk2(cx * inv, cy * inv);
                    }
                }
            }
        }
        __syncthreads();

        // ---- Wo + residual + LN1 + FF1 + FF2 + residual + LN2, per row, packed ----
        if (tid < SS) {
            const u64* ctx_u64 = reinterpret_cast<const u64*>(s_att);
            u64 c2[8];
            #pragma unroll
            for (int j = 0; j < 8; j++) c2[j] = ctx_u64[j * TSTR + tid];

            const float4* h4 = reinterpret_cast<const float4*>(&s_h[tid * HSTR]);
            float4 hr4[4] = {h4[0], h4[1], h4[2], h4[3]};
            const float* hs = reinterpret_cast<const float*>(hr4);

            const u64* wo2 = reinterpret_cast<const u64*>(s_Wo);
            float vv[16];
            float mu = 0.f;
            #pragma unroll
            for (int o = 0; o < 16; o++) {
                vv[o] = dot16p(c2, wo2 + o * 8, s_bo[o]) + hs[o];
                mu += vv[o];
            }
            mu *= 0.0625f;
            float var = 0.f;
            #pragma unroll
            for (int d = 0; d < 16; d++) { float t = vv[d] - mu; var = fmaf(t, t, var); }
            float r = rsqrtf(fmaf(var, 0.0625f, 1e-5f));

            float ln1s[16];
            #pragma unroll
            for (int d = 0; d < 16; d++)
                ln1s[d] = (vv[d] - mu) * r * s_ln[d] + s_ln[16 + d];
            u64 l2[8];
            #pragma unroll
            for (int j = 0; j < 8; j++) l2[j] = pk2(ln1s[2*j], ln1s[2*j+1]);

            const u64* w12 = reinterpret_cast<const u64*>(s_W1);
            float frs[16];
            #pragma unroll
            for (int f = 0; f < 16; f++)
                frs[f] = fmaxf(dot16p(l2, w12 + f * 8, s_b1[f]), 0.f);
            u64 f2[8];
            #pragma unroll
            for (int j = 0; j < 8; j++) f2[j] = pk2(frs[2*j], frs[2*j+1]);

            const u64* w22 = reinterpret_cast<const u64*>(s_W2);
            mu = 0.f;
            #pragma unroll
            for (int d = 0; d < 16; d++) {
                vv[d] = dot16p(f2, w22 + d * 8, s_b2[d]) + ln1s[d];
                mu += vv[d];
            }
            mu *= 0.0625f;
            var = 0.f;
            #pragma unroll
            for (int d = 0; d < 16; d++) { float t = vv[d] - mu; var = fmaf(t, t, var); }
            r = rsqrtf(fmaf(var, 0.0625f, 1e-5f));

            float4 ov[4];
            float* os = reinterpret_cast<float*>(ov);
            #pragma unroll
            for (int d = 0; d < 16; d++)
                os[d] = (vv[d] - mu) * r * s_ln[32 + d] + s_ln[48 + d];
            float4* oh = reinterpret_cast<float4*>(&s_h[tid * HSTR]);
            oh[0] = ov[0]; oh[1] = ov[1]; oh[2] = ov[2]; oh[3] = ov[3];
        }
        __syncthreads();
    }

    // ---------- final LN (cls row) ----------
    if (tid == 0) {
        float mu = 0.f;
        #pragma unroll
        for (int d = 0; d < 16; d++) mu += s_h[d];
        mu *= 0.0625f;
        float var = 0.f;
        #pragma unroll
        for (int d = 0; d < 16; d++) { float t = s_h[d] - mu; var = fmaf(t, t, var); }
        float r = rsqrtf(fmaf(var, 0.0625f, 1e-5f));
        #pragma unroll
        for (int d = 0; d < 16; d++)
            s_att[d] = (s_h[d] - mu) * r * lnf_g[d] + lnf_b[d];
    }
    __syncthreads();

    // ---------- end projection (fused with head weight) ----------
    if (tid < 100) {
        float acc = end_b[tid];
        #pragma unroll
        for (int d = 0; d < 16; d++) acc = fmaf(s_att[d], end_w[tid * 16 + d], acc);
        s_att[64 + tid] = acc * head_w[tid];
    }
    __syncthreads();

    // ---------- head sum + sigmoid ----------
    if (tid == 0) {
        float acc = head_b[0];
        #pragma unroll 4
        for (int j = 0; j < 100; j++) acc += s_att[64 + j];
        out[b] = 1.f / (1.f + ex2f_fast(-acc * 1.44269504088896f));
    }
}

extern "C" void kernel_launch(void* const* d_in, const int* in_sizes, int n_in,
                              void* d_out, int out_size) {
    const float* x       = (const float*)d_in[0];
    const float* conv_w  = (const float*)d_in[1];
    const float* conv_b  = (const float*)d_in[2];
    const float* cls_emb = (const float*)d_in[3];
    const float* Wqkv    = (const float*)d_in[4];
    const float* bqkv    = (const float*)d_in[5];
    const float* Wo      = (const float*)d_in[6];
    const float* bo      = (const float*)d_in[7];
    const float* W1      = (const float*)d_in[8];
    const float* b1      = (const float*)d_in[9];
    const float* W2      = (const float*)d_in[10];
    const float* b2      = (const float*)d_in[11];
    const float* ln1_g   = (const float*)d_in[12];
    const float* ln1_b   = (const float*)d_in[13];
    const float* ln2_g   = (const float*)d_in[14];
    const float* ln2_b   = (const float*)d_in[15];
    const float* lnf_g   = (const float*)d_in[16];
    const float* lnf_b   = (const float*)d_in[17];
    const float* end_w   = (const float*)d_in[18];
    const float* end_b   = (const float*)d_in[19];
    const float* head_w  = (const float*)d_in[20];
    const float* head_b  = (const float*)d_in[21];

    int B = in_sizes[0] / SEQIN;

    TorrinE0_fused_kernel<<<B, NT>>>(
        x, conv_w, conv_b, cls_emb, Wqkv, bqkv, Wo, bo, W1, b1, W2, b2,
        ln1_g, ln1_b, ln2_g, ln2_b, lnf_g, lnf_b, end_w, end_b, head_w, head_b,
        (float*)d_out);
}